// round 2
// baseline (speedup 1.0000x reference)
#include <cuda_runtime.h>
#include <math.h>

#define TT 64
#define DD 3136
#define HH 512
#define EPSF 1e-6f

// ---------------------------------------------------------------------------
// Scratch: one big static device buffer, sub-sliced on the host.
// ---------------------------------------------------------------------------
#define OFF_NK      0
#define OFF_NV      200704
#define OFF_KEYS    401408
#define OFF_VALS    602112
#define OFF_Y       802816
#define OFF_GY      1003520
#define OFF_C2      1204224
#define OFF_YPW2    1404928
#define OFF_PART0   1605632   /* 3*T*D  */
#define OFF_PART1   2207744   /* 3*T*D  */
#define OFF_PARTD   2809856   /* 3*T*D  (reused: y-part then y'-part) */
#define OFF_PARTH   3411968   /* 18*T*H (reused: z1-part then gh-part) */
#define OFF_Z1      4001792
#define OFF_H       4034560
#define OFF_GZ1     4067328
#define OFF_C1      4100096
#define OFF_HP      4132864
#define OFF_KKPART  4165632   /* 49*64*64 */
#define OFF_KK      4366336
#define OFF_HHM     4370432
#define OFF_GYSUM   4374528
#define OFF_SCD     4377664
#define OFF_GZ1SUM  4380800
#define OFF_INV     4381312
#define OFF_S       4381376
#define SCRATCH_FLOATS 4381440

__device__ float g_scratch[SCRATCH_FLOATS];

// ---------------------------------------------------------------------------
// Math helpers (flax approximate gelu)
// ---------------------------------------------------------------------------
__device__ __forceinline__ float geluf(float x) {
    float x2 = x * x;
    float u = 0.7978845608028654f * (x + 0.044715f * x2 * x);
    float th = tanhf(u);
    return 0.5f * x * (1.0f + th);
}
__device__ __forceinline__ float gelugradf(float x) {
    float x2 = x * x;
    float u = 0.7978845608028654f * (x + 0.044715f * x2 * x);
    float th = tanhf(u);
    return 0.5f * (1.0f + th) +
           0.5f * x * (1.0f - th * th) * 0.7978845608028654f * (1.0f + 0.134145f * x2);
}

// ---------------------------------------------------------------------------
// K1: 3x3 SAME conv (4->4) + per-pixel channel RMSNorm, K and V branches.
// One block per token t, one thread per pixel (784 threads).
// ---------------------------------------------------------------------------
__global__ void conv_rms_kernel(const float* __restrict__ x,
                                const float* __restrict__ wk, const float* __restrict__ bk,
                                const float* __restrict__ wv, const float* __restrict__ bv,
                                const float* __restrict__ sck, const float* __restrict__ scv,
                                float* __restrict__ nk, float* __restrict__ nv) {
    __shared__ float swk[144], swv[144], ssk[4], ssv[4], sbk[4], sbv[4];
    int t = blockIdx.x;
    int tid = threadIdx.x;
    if (tid < 144) { swk[tid] = wk[tid]; swv[tid] = wv[tid]; }
    if (tid < 4) { ssk[tid] = sck[tid]; ssv[tid] = scv[tid]; sbk[tid] = bk[tid]; sbv[tid] = bv[tid]; }
    __syncthreads();
    int i = tid / 28, j = tid % 28;
    float ak[4], av[4];
#pragma unroll
    for (int c = 0; c < 4; c++) { ak[c] = sbk[c]; av[c] = sbv[c]; }
    const float* xb = x + t * DD;
#pragma unroll
    for (int ci = 0; ci < 4; ci++) {
        const float* xc = xb + ci * 784;
#pragma unroll
        for (int di = 0; di < 3; di++) {
            int ii = i + di - 1;
            if (ii < 0 || ii >= 28) continue;
#pragma unroll
            for (int dj = 0; dj < 3; dj++) {
                int jj = j + dj - 1;
                if (jj < 0 || jj >= 28) continue;
                float xv = xc[ii * 28 + jj];
                int wb = ((di * 3 + dj) * 4 + ci) * 4;
#pragma unroll
                for (int co = 0; co < 4; co++) {
                    ak[co] += xv * swk[wb + co];
                    av[co] += xv * swv[wb + co];
                }
            }
        }
    }
    float mk = 0.f, mv = 0.f;
#pragma unroll
    for (int c = 0; c < 4; c++) { mk += ak[c] * ak[c]; mv += av[c] * av[c]; }
    float ik = rsqrtf(mk * 0.25f + EPSF);
    float iv = rsqrtf(mv * 0.25f + EPSF);
    int o = t * DD + tid * 4;
#pragma unroll
    for (int c = 0; c < 4; c++) {
        nk[o + c] = ak[c] * ik * ssk[c];
        nv[o + c] = av[c] * iv * ssv[c];
    }
}

// ---------------------------------------------------------------------------
// Generic fp32 GEMM, M fixed = 64, tiles 64x64, BK=16, split-K via blockIdx.y.
// A: (64, K) row-major lda=K.  B: (K, N) ldb given, or transB: B is (N, K).
// Writes partial sums per split to Cpart[split][64][N].
// ---------------------------------------------------------------------------
#define BK 16
#define SST 68

__global__ void __launch_bounds__(256, 2)
gemm64(const float* __restrict__ A, const float* __restrict__ B,
       float* __restrict__ Cpart, int K, int N, int ldb,
       int totalSteps, int stepsPerSplit, int transB) {
    __shared__ __align__(16) float As[BK * SST];
    __shared__ __align__(16) float Bs[BK * SST];
    int tid = threadIdx.x;
    int n0 = blockIdx.x * 64;
    int split = blockIdx.y;
    int s0 = split * stepsPerSplit;
    int s1 = min(s0 + stepsPerSplit, totalSteps);

    float c[4][4] = {};
    int ty = tid >> 4, tx = tid & 15;
    int m0 = ty * 4, nn0 = tx * 4;

    int aRow = tid >> 2;        // 0..63
    int aCol = (tid & 3) * 4;   // 0,4,8,12
    int bRow = tid >> 4;        // 0..15
    int bCol = (tid & 15) * 4;  // 0..60

    float4 aR = make_float4(0, 0, 0, 0), bR = make_float4(0, 0, 0, 0);
    if (s0 < s1) {
        int k0 = s0 * BK;
        aR = *(const float4*)(A + aRow * K + k0 + aCol);
        if (!transB) bR = *(const float4*)(B + (k0 + bRow) * ldb + n0 + bCol);
        else         bR = *(const float4*)(B + (n0 + aRow) * ldb + k0 + aCol);
    }
    for (int step = s0; step < s1; ++step) {
        As[(aCol + 0) * SST + aRow] = aR.x;
        As[(aCol + 1) * SST + aRow] = aR.y;
        As[(aCol + 2) * SST + aRow] = aR.z;
        As[(aCol + 3) * SST + aRow] = aR.w;
        if (!transB) {
            *(float4*)(Bs + bRow * SST + bCol) = bR;
        } else {
            Bs[(aCol + 0) * SST + aRow] = bR.x;
            Bs[(aCol + 1) * SST + aRow] = bR.y;
            Bs[(aCol + 2) * SST + aRow] = bR.z;
            Bs[(aCol + 3) * SST + aRow] = bR.w;
        }
        __syncthreads();
        if (step + 1 < s1) {
            int k0 = (step + 1) * BK;
            aR = *(const float4*)(A + aRow * K + k0 + aCol);
            if (!transB) bR = *(const float4*)(B + (k0 + bRow) * ldb + n0 + bCol);
            else         bR = *(const float4*)(B + (n0 + aRow) * ldb + k0 + aCol);
        }
#pragma unroll
        for (int kk = 0; kk < BK; ++kk) {
            float4 a = *(const float4*)(As + kk * SST + m0);
            float4 b = *(const float4*)(Bs + kk * SST + nn0);
            c[0][0] += a.x * b.x; c[0][1] += a.x * b.y; c[0][2] += a.x * b.z; c[0][3] += a.x * b.w;
            c[1][0] += a.y * b.x; c[1][1] += a.y * b.y; c[1][2] += a.y * b.z; c[1][3] += a.y * b.w;
            c[2][0] += a.z * b.x; c[2][1] += a.z * b.y; c[2][2] += a.z * b.z; c[2][3] += a.z * b.w;
            c[3][0] += a.w * b.x; c[3][1] += a.w * b.y; c[3][2] += a.w * b.z; c[3][3] += a.w * b.w;
        }
        __syncthreads();
    }
    float* Cp = Cpart + (size_t)split * 64 * N;
#pragma unroll
    for (int i = 0; i < 4; i++) {
        float4 v = make_float4(c[i][0], c[i][1], c[i][2], c[i][3]);
        *(float4*)(Cp + (m0 + i) * N + n0 + nn0) = v;
    }
}

// Sum split-K partials + optional bias.
__global__ void combine_kernel(const float* __restrict__ part, const float* __restrict__ bias,
                               float* __restrict__ C, int N, int splits) {
    int idx = blockIdx.x * blockDim.x + threadIdx.x;
    if (idx >= 64 * N) return;
    float s = 0.f;
    for (int p = 0; p < splits; p++) s += part[(size_t)p * 64 * N + idx];
    if (bias) s += bias[idx % N];
    C[idx] = s;
}

// Fused: z1 = sum(part) + b1 ; h = gelu(z1). Writes both (z1 reused later).
__global__ void combine_gelu_kernel(const float* __restrict__ part, const float* __restrict__ bias,
                                    float* __restrict__ z1, float* __restrict__ h, int splits) {
    int idx = blockIdx.x * 256 + threadIdx.x;
    if (idx >= TT * HH) return;
    float s = 0.f;
    for (int p = 0; p < splits; p++) s += part[(size_t)p * TT * HH + idx];
    s += bias[idx % HH];
    z1[idx] = s;
    h[idx] = geluf(s);
}

// Fused: gh = sum(part) ; gz1 = gh * gelu'(z1). gh never materialized.
__global__ void combine_gz1_kernel(const float* __restrict__ part, const float* __restrict__ z1,
                                   float* __restrict__ gz1, int splits) {
    int idx = blockIdx.x * 256 + threadIdx.x;
    if (idx >= TT * HH) return;
    float s = 0.f;
    for (int p = 0; p < splits; p++) s += part[(size_t)p * TT * HH + idx];
    gz1[idx] = s * gelugradf(z1[idx]);
}

// ---------------------------------------------------------------------------
// Elementwise + reductions
// ---------------------------------------------------------------------------
// per-token: inv = rsqrt(mean(y^2)+eps); s = sum(gp*sc*y), gp = 2(y*inv*sc - v)
__global__ void invs_kernel(const float* __restrict__ y, const float* __restrict__ v,
                            const float* __restrict__ sc,
                            float* __restrict__ invA, float* __restrict__ sA) {
    int t = blockIdx.x, tid = threadIdx.x;
    __shared__ float red[256];
    __shared__ float sinv;
    float acc = 0.f;
    for (int d = tid; d < DD; d += 256) { float yv = y[t * DD + d]; acc += yv * yv; }
    red[tid] = acc; __syncthreads();
    for (int st = 128; st > 0; st >>= 1) { if (tid < st) red[tid] += red[tid + st]; __syncthreads(); }
    if (tid == 0) { sinv = rsqrtf(red[0] * (1.0f / DD) + EPSF); invA[t] = sinv; }
    __syncthreads();
    float inv = sinv;
    acc = 0.f;
    for (int d = tid; d < DD; d += 256) {
        float yv = y[t * DD + d], scd = sc[d];
        float gp = 2.f * (yv * inv * scd - v[t * DD + d]);
        acc += gp * scd * yv;
    }
    __syncthreads();
    red[tid] = acc; __syncthreads();
    for (int st = 128; st > 0; st >>= 1) { if (tid < st) red[tid] += red[tid + st]; __syncthreads(); }
    if (tid == 0) sA[t] = red[0];
}

__global__ void gy_kernel(const float* __restrict__ y, const float* __restrict__ v,
                          const float* __restrict__ sc, const float* __restrict__ invA,
                          const float* __restrict__ sA, float* __restrict__ gy) {
    int idx = blockIdx.x * 256 + threadIdx.x;
    if (idx >= TT * DD) return;
    int t = idx / DD, d = idx - t * DD;
    float inv = invA[t], sv = sA[t];
    float yv = y[idx], scd = sc[d];
    float gp = 2.f * (yv * inv * scd - v[idx]);
    gy[idx] = inv * scd * gp - inv * inv * inv * sv * (1.0f / DD) * yv;
}

// column sums over tokens: gysum[d] = sum_t gy ; scd[d] = sum_t gp*y*inv (scale grad)
__global__ void colsumD_kernel(const float* __restrict__ gy, const float* __restrict__ y,
                               const float* __restrict__ v, const float* __restrict__ sc,
                               const float* __restrict__ invA,
                               float* __restrict__ gysum, float* __restrict__ scd_out) {
    int d = blockIdx.x * 256 + threadIdx.x;
    if (d >= DD) return;
    float gs = 0.f, sd = 0.f;
    float scd = sc[d];
    for (int t = 0; t < TT; t++) {
        int idx = t * DD + d;
        gs += gy[idx];
        float inv = invA[t];
        float yv = y[idx];
        float gp = 2.f * (yv * inv * scd - v[idx]);
        sd += gp * yv * inv;
    }
    gysum[d] = gs; scd_out[d] = sd;
}

__global__ void colsumH_kernel(const float* __restrict__ gz1, float* __restrict__ gz1sum) {
    int h = blockIdx.x * 256 + threadIdx.x;
    if (h >= HH) return;
    float s = 0.f;
    for (int t = 0; t < TT; t++) s += gz1[t * HH + h];
    gz1sum[h] = s;
}

// C1[t,n] = sum_s KK[t,s] * gz1[s,n]
__global__ void kkgz1_kernel(const float* __restrict__ KK, const float* __restrict__ gz1,
                             float* __restrict__ C1) {
    int t = blockIdx.x, tid = threadIdx.x;
    __shared__ float row[64];
    if (tid < 64) row[tid] = KK[t * 64 + tid];
    __syncthreads();
    for (int n = tid; n < HH; n += 256) {
        float acc = 0.f;
#pragma unroll 16
        for (int s = 0; s < 64; s++) acc += row[s] * gz1[s * HH + n];
        C1[t * HH + n] = acc;
    }
}

__global__ void z1p_kernel(const float* __restrict__ z1, const float* __restrict__ C1,
                           const float* __restrict__ gz1sum, float cc, float* __restrict__ hp) {
    int idx = blockIdx.x * 256 + threadIdx.x;
    if (idx >= TT * HH) return;
    int h = idx % HH;
    float z = z1[idx] - cc * (C1[idx] + gz1sum[h]);
    hp[idx] = geluf(z);
}

// HHm[t,s] = dot(hp[t,:], h[s,:])
__global__ void hh_kernel(const float* __restrict__ hp, const float* __restrict__ h,
                          float* __restrict__ HHm) {
    int t = blockIdx.x, tid = threadIdx.x;
    __shared__ float row[HH];
    for (int j = tid; j < HH; j += 64) row[j] = hp[t * HH + j];
    __syncthreads();
    int s = tid;
    float a0 = 0.f, a1 = 0.f, a2 = 0.f, a3 = 0.f;
    for (int j = 0; j < HH; j += 4) {
        a0 += row[j + 0] * h[s * HH + j + 0];
        a1 += row[j + 1] * h[s * HH + j + 1];
        a2 += row[j + 2] * h[s * HH + j + 2];
        a3 += row[j + 3] * h[s * HH + j + 3];
    }
    HHm[t * 64 + s] = a0 + a1 + a2 + a3;
}

// C2[t,n] = sum_s HHm[t,s] * gy[s,n]
__global__ void c2_kernel(const float* __restrict__ HHm, const float* __restrict__ gy,
                          float* __restrict__ C2) {
    int t = blockIdx.x, tid = threadIdx.x;
    __shared__ float row[64];
    if (tid < 64) row[tid] = HHm[t * 64 + tid];
    __syncthreads();
    for (int n = tid; n < DD; n += 256) {
        float acc = 0.f;
#pragma unroll 16
        for (int s = 0; s < 64; s++) acc += row[s] * gy[s * DD + n];
        C2[t * DD + n] = acc;
    }
}

// Final: y' = ypw2 - cc*(C2+gysum); pred = rmsnorm(y', sc - cc*scdelta);
// out = rmsnorm(pred, out_scale). Output layout == Y layout (reshape is a no-op).
__global__ void final_kernel(const float* __restrict__ ypw2, const float* __restrict__ C2,
                             const float* __restrict__ gysum, const float* __restrict__ scdelta,
                             const float* __restrict__ sc, const float* __restrict__ outsc,
                             float cc, float* __restrict__ out) {
    int t = blockIdx.x, tid = threadIdx.x;
    __shared__ float buf[DD];
    __shared__ float red[256];
    __shared__ float sval;
    float acc = 0.f;
    for (int d = tid; d < DD; d += 256) {
        float v = ypw2[t * DD + d] - cc * (C2[t * DD + d] + gysum[d]);
        buf[d] = v; acc += v * v;
    }
    red[tid] = acc; __syncthreads();
    for (int st = 128; st > 0; st >>= 1) { if (tid < st) red[tid] += red[tid + st]; __syncthreads(); }
    if (tid == 0) sval = rsqrtf(red[0] * (1.0f / DD) + EPSF);
    __syncthreads();
    float inva = sval;
    acc = 0.f;
    for (int d = tid; d < DD; d += 256) {
        float p = buf[d] * inva * (sc[d] - cc * scdelta[d]);
        buf[d] = p; acc += p * p;
    }
    __syncthreads();
    red[tid] = acc; __syncthreads();
    for (int st = 128; st > 0; st >>= 1) { if (tid < st) red[tid] += red[tid + st]; __syncthreads(); }
    if (tid == 0) sval = rsqrtf(red[0] * (1.0f / DD) + EPSF);
    __syncthreads();
    float invb = sval;
    for (int d = tid; d < DD; d += 256)
        out[t * DD + d] = buf[d] * invb * outsc[d];
}

// ---------------------------------------------------------------------------
// Host orchestration
// ---------------------------------------------------------------------------
extern "C" void kernel_launch(void* const* d_in, const int* in_sizes, int n_in,
                              void* d_out, int out_size) {
    const float* x          = (const float*)d_in[0];
    const float* conv_k_w   = (const float*)d_in[1];
    const float* conv_k_b   = (const float*)d_in[2];
    const float* conv_v_w   = (const float*)d_in[3];
    const float* conv_v_b   = (const float*)d_in[4];
    const float* rms_k_sc   = (const float*)d_in[5];
    const float* rms_v_sc   = (const float*)d_in[6];
    const float* dense_k_w  = (const float*)d_in[7];
    const float* dense_k_b  = (const float*)d_in[8];
    const float* dense_v_w  = (const float*)d_in[9];
    const float* dense_v_b  = (const float*)d_in[10];
    const float* mem_w1     = (const float*)d_in[11];
    const float* mem_b1     = (const float*)d_in[12];
    const float* mem_w2     = (const float*)d_in[13];
    const float* mem_b2     = (const float*)d_in[14];
    const float* mem_scale  = (const float*)d_in[15];
    const float* rms_out_sc = (const float*)d_in[16];
    float* out = (float*)d_out;

    float* S = nullptr;
    cudaGetSymbolAddress((void**)&S, g_scratch);

    float* nk     = S + OFF_NK;     float* nv     = S + OFF_NV;
    float* keys   = S + OFF_KEYS;   float* vals   = S + OFF_VALS;
    float* y      = S + OFF_Y;      float* gy     = S + OFF_GY;
    float* C2     = S + OFF_C2;     float* ypw2   = S + OFF_YPW2;
    float* part0  = S + OFF_PART0;  float* part1  = S + OFF_PART1;
    float* partD  = S + OFF_PARTD;  float* partH  = S + OFF_PARTH;
    float* z1     = S + OFF_Z1;     float* h      = S + OFF_H;
    float* gz1    = S + OFF_GZ1;    float* C1     = S + OFF_C1;
    float* hp     = S + OFF_HP;
    float* kkpart = S + OFF_KKPART; float* KK     = S + OFF_KK;
    float* HHm    = S + OFF_HHM;    float* gysum  = S + OFF_GYSUM;
    float* scd    = S + OFF_SCD;    float* gz1sum = S + OFF_GZ1SUM;
    float* invA   = S + OFF_INV;    float* sA     = S + OFF_S;

    float cc = (float)(1e-4 * 0.1 * pow(0.9, 63.0));

    // 1. conv + channel RMSNorm (K and V branches)
    conv_rms_kernel<<<TT, 784>>>(x, conv_k_w, conv_k_b, conv_v_w, conv_v_b,
                                 rms_k_sc, rms_v_sc, nk, nv);

    // 2. keys = nk @ Wk + bk ; vals = nv @ Wv + bv    (split-K = 3)
    gemm64<<<dim3(49, 3), 256>>>(nk, dense_k_w, part0, DD, DD, DD, 196, 66, 0);
    gemm64<<<dim3(49, 3), 256>>>(nv, dense_v_w, part1, DD, DD, DD, 196, 66, 0);
    combine_kernel<<<784, 256>>>(part0, dense_k_b, keys, DD, 3);
    combine_kernel<<<784, 256>>>(part1, dense_v_b, vals, DD, 3);

    // 3. z1 = keys @ W1 + b1 ; h = gelu(z1)           (split-K = 18, fused combine+gelu)
    gemm64<<<dim3(8, 18), 256>>>(keys, mem_w1, partH, DD, HH, HH, 196, 11, 0);
    combine_gelu_kernel<<<128, 256>>>(partH, mem_b1, z1, h, 18);

    // 4. y = h @ W2 + b2                              (split-K = 3)
    gemm64<<<dim3(49, 3), 256>>>(h, mem_w2, partD, HH, DD, DD, 32, 11, 0);
    combine_kernel<<<784, 256>>>(partD, mem_b2, y, DD, 3);

    // 5. RMSNorm backward pieces
    invs_kernel<<<TT, 256>>>(y, vals, mem_scale, invA, sA);
    gy_kernel<<<784, 256>>>(y, vals, mem_scale, invA, sA, gy);
    colsumD_kernel<<<13, 256>>>(gy, y, vals, mem_scale, invA, gysum, scd);

    // 6. gh = gy @ W2^T ; gz1 = gh * gelu'(z1)        (fused combine+gelu')
    gemm64<<<dim3(8, 18), 256>>>(gy, mem_w2, partH, DD, HH, DD, 196, 11, 1);
    combine_gz1_kernel<<<128, 256>>>(partH, z1, gz1, 18);
    colsumH_kernel<<<2, 256>>>(gz1, gz1sum);

    // 7. KK = keys @ keys^T ; C1 = KK @ gz1 ; hp = gelu(z1 - cc*(C1 + gz1sum))
    gemm64<<<dim3(1, 49), 256>>>(keys, keys, kkpart, DD, 64, DD, 196, 4, 1);
    combine_kernel<<<16, 256>>>(kkpart, nullptr, KK, 64, 49);
    kkgz1_kernel<<<TT, 256>>>(KK, gz1, C1);
    z1p_kernel<<<128, 256>>>(z1, C1, gz1sum, cc, hp);

    // 8. y'W2 = hp @ W2 + b2 ; HHm = hp @ h^T ; C2 = HHm @ gy
    gemm64<<<dim3(49, 3), 256>>>(hp, mem_w2, partD, HH, DD, DD, 32, 11, 0);
    combine_kernel<<<784, 256>>>(partD, mem_b2, ypw2, DD, 3);
    hh_kernel<<<TT, 64>>>(hp, h, HHm);
    c2_kernel<<<TT, 256>>>(HHm, gy, C2);

    // 9. final: corrections + double RMSNorm + output
    final_kernel<<<TT, 256>>>(ypw2, C2, gysum, scd, mem_scale, rms_out_sc, cc, out);

    (void)in_sizes; (void)n_in; (void)out_size;
}

// round 15
// speedup vs baseline: 1.1665x; 1.1665x over previous
#include <cuda_runtime.h>
#include <math.h>

#define TT 64
#define DD 3136
#define HH 512
#define EPSF 1e-6f

// ---------------------------------------------------------------------------
// Scratch offsets (floats)
// ---------------------------------------------------------------------------
#define OFF_NK      0
#define OFF_NV      200704
#define OFF_KEYS    401408
#define OFF_VALS    602112
#define OFF_Y       802816
#define OFF_GY      1003520
#define OFF_PART0   1204224   /* 14*T*D */
#define OFF_PART1   4014080   /* 14*T*D */
#define OFF_PARTD   6823936   /*  8*T*D (y-part, then y'-part) */
#define OFF_PARTH   8429568   /* 18*T*H (z1-part, then gh-part) */
#define OFF_Z1      9019392
#define OFF_H       9052160
#define OFF_GZ1     9084928
#define OFF_HP      9117696
#define OFF_KKPART  9150464   /* 49*64*64 */
#define OFF_KK      9351168
#define OFF_HHM     9355264
#define OFF_GYSUM   9359360
#define OFF_SCD     9362496
#define OFF_GZ1SUM  9365632
#define OFF_INV     9366144
#define OFF_S       9366208
#define SCRATCH_FLOATS 9366272

__device__ float g_scratch[SCRATCH_FLOATS];

// ---------------------------------------------------------------------------
// Math helpers
// ---------------------------------------------------------------------------
__device__ __forceinline__ float geluf(float x) {
    float x2 = x * x;
    float u = 0.7978845608028654f * (x + 0.044715f * x2 * x);
    float th = tanhf(u);
    return 0.5f * x * (1.0f + th);
}
__device__ __forceinline__ float gelugradf(float x) {
    float x2 = x * x;
    float u = 0.7978845608028654f * (x + 0.044715f * x2 * x);
    float th = tanhf(u);
    return 0.5f * (1.0f + th) +
           0.5f * x * (1.0f - th * th) * 0.7978845608028654f * (1.0f + 0.134145f * x2);
}

// packed f32x2 helpers (Blackwell double-rate fp32)
__device__ __forceinline__ unsigned long long pack2(float lo, float hi) {
    unsigned long long r;
    asm("mov.b64 %0, {%1, %2};" : "=l"(r) : "f"(lo), "f"(hi));
    return r;
}
__device__ __forceinline__ void unpack2(unsigned long long v, float& lo, float& hi) {
    asm("mov.b64 {%0, %1}, %2;" : "=f"(lo), "=f"(hi) : "l"(v));
}
__device__ __forceinline__ void ffma2(unsigned long long& d, unsigned long long a, unsigned long long b) {
    asm("fma.rn.f32x2 %0, %1, %2, %0;" : "+l"(d) : "l"(a), "l"(b));
}

// ---------------------------------------------------------------------------
// conv 3x3 SAME (4->4) + per-pixel channel RMSNorm, K and V branches.
// ---------------------------------------------------------------------------
__global__ void conv_rms_kernel(const float* __restrict__ x,
                                const float* __restrict__ wk, const float* __restrict__ bk,
                                const float* __restrict__ wv, const float* __restrict__ bv,
                                const float* __restrict__ sck, const float* __restrict__ scv,
                                float* __restrict__ nk, float* __restrict__ nv) {
    __shared__ float swk[144], swv[144], ssk[4], ssv[4], sbk[4], sbv[4];
    int t = blockIdx.x;
    int tid = threadIdx.x;
    if (tid < 144) { swk[tid] = wk[tid]; swv[tid] = wv[tid]; }
    if (tid < 4) { ssk[tid] = sck[tid]; ssv[tid] = scv[tid]; sbk[tid] = bk[tid]; sbv[tid] = bv[tid]; }
    __syncthreads();
    int i = tid / 28, j = tid % 28;
    float ak[4], av[4];
#pragma unroll
    for (int c = 0; c < 4; c++) { ak[c] = sbk[c]; av[c] = sbv[c]; }
    const float* xb = x + t * DD;
#pragma unroll
    for (int ci = 0; ci < 4; ci++) {
        const float* xc = xb + ci * 784;
#pragma unroll
        for (int di = 0; di < 3; di++) {
            int ii = i + di - 1;
            if (ii < 0 || ii >= 28) continue;
#pragma unroll
            for (int dj = 0; dj < 3; dj++) {
                int jj = j + dj - 1;
                if (jj < 0 || jj >= 28) continue;
                float xv = xc[ii * 28 + jj];
                int wb = ((di * 3 + dj) * 4 + ci) * 4;
#pragma unroll
                for (int co = 0; co < 4; co++) {
                    ak[co] += xv * swk[wb + co];
                    av[co] += xv * swv[wb + co];
                }
            }
        }
    }
    float mk = 0.f, mv = 0.f;
#pragma unroll
    for (int c = 0; c < 4; c++) { mk += ak[c] * ak[c]; mv += av[c] * av[c]; }
    float ik = rsqrtf(mk * 0.25f + EPSF);
    float iv = rsqrtf(mv * 0.25f + EPSF);
    int o = t * DD + tid * 4;
#pragma unroll
    for (int c = 0; c < 4; c++) {
        nk[o + c] = ak[c] * ik * ssk[c];
        nv[o + c] = av[c] * iv * ssv[c];
    }
}

// ---------------------------------------------------------------------------
// Wide GEMM: M=64 fixed, N-tile 224, BK=16, FFMA2 inner product.
// A: (64, K) row-major.  B: (K, N) row-major, ldb = N.  Split-K -> Cpart.
// 224 threads; per-thread 8x8 micro-tile (rows ty*4 & 32+ty*4, cols tx*4 & 112+tx*4).
// ---------------------------------------------------------------------------
#define WN 224
#define WBK 16
#define APAD 68
#define BPAD 228

__global__ void __launch_bounds__(224, 2)
gemmw(const float* __restrict__ A, const float* __restrict__ B,
      float* __restrict__ Cpart, int K, int N, int ldb,
      int totalSteps, int stepsPerSplit) {
    __shared__ __align__(16) float As[WBK * APAD];
    __shared__ __align__(16) float Bs[WBK * BPAD];
    int tid = threadIdx.x;
    int n0 = blockIdx.x * WN;
    int split = blockIdx.y;
    int s0 = split * stepsPerSplit;
    int s1 = min(s0 + stepsPerSplit, totalSteps);

    int ty = tid / 28;      // 0..7
    int tx = tid - ty * 28; // 0..27
    int mA = ty * 4, mB = 32 + ty * 4;
    int nA = tx * 4, nB = 112 + tx * 4;

    unsigned long long c[8][4];
#pragma unroll
    for (int i = 0; i < 8; i++)
#pragma unroll
        for (int j = 0; j < 4; j++) c[i][j] = 0ull;

    // prefetch registers
    float4 aP0 = make_float4(0, 0, 0, 0), aP1 = make_float4(0, 0, 0, 0);
    float4 bP[4];
#pragma unroll
    for (int i = 0; i < 4; i++) bP[i] = make_float4(0, 0, 0, 0);
    int am0 = tid >> 2, aj0 = (tid & 3) * 4;      // chunk idx = tid
    int am1 = (tid + 224) >> 2, aj1 = ((tid + 224) & 3) * 4;
    bool hasA1 = (tid < 32);

    if (s0 < s1) {
        int k0 = s0 * WBK;
        aP0 = *(const float4*)(A + am0 * K + k0 + aj0);
        if (hasA1) aP1 = *(const float4*)(A + am1 * K + k0 + aj1);
#pragma unroll
        for (int i = 0; i < 4; i++) {
            int idx = tid + 224 * i;
            int kk = idx / 56, c4 = idx - kk * 56;
            bP[i] = *(const float4*)(B + (k0 + kk) * ldb + n0 + c4 * 4);
        }
    }

    for (int step = s0; step < s1; ++step) {
        // stage prefetched data to smem
        As[(aj0 + 0) * APAD + am0] = aP0.x;
        As[(aj0 + 1) * APAD + am0] = aP0.y;
        As[(aj0 + 2) * APAD + am0] = aP0.z;
        As[(aj0 + 3) * APAD + am0] = aP0.w;
        if (hasA1) {
            As[(aj1 + 0) * APAD + am1] = aP1.x;
            As[(aj1 + 1) * APAD + am1] = aP1.y;
            As[(aj1 + 2) * APAD + am1] = aP1.z;
            As[(aj1 + 3) * APAD + am1] = aP1.w;
        }
#pragma unroll
        for (int i = 0; i < 4; i++) {
            int idx = tid + 224 * i;
            int kk = idx / 56, c4 = idx - kk * 56;
            *(float4*)(Bs + kk * BPAD + c4 * 4) = bP[i];
        }
        __syncthreads();
        if (step + 1 < s1) {
            int k0 = (step + 1) * WBK;
            aP0 = *(const float4*)(A + am0 * K + k0 + aj0);
            if (hasA1) aP1 = *(const float4*)(A + am1 * K + k0 + aj1);
#pragma unroll
            for (int i = 0; i < 4; i++) {
                int idx = tid + 224 * i;
                int kk = idx / 56, c4 = idx - kk * 56;
                bP[i] = *(const float4*)(B + (k0 + kk) * ldb + n0 + c4 * 4);
            }
        }
#pragma unroll
        for (int kk = 0; kk < WBK; ++kk) {
            float4 a0 = *(const float4*)(As + kk * APAD + mA);
            float4 a1 = *(const float4*)(As + kk * APAD + mB);
            float4 b0 = *(const float4*)(Bs + kk * BPAD + nA);
            float4 b1 = *(const float4*)(Bs + kk * BPAD + nB);
            unsigned long long bp[4];
            bp[0] = pack2(b0.x, b0.y); bp[1] = pack2(b0.z, b0.w);
            bp[2] = pack2(b1.x, b1.y); bp[3] = pack2(b1.z, b1.w);
            unsigned long long ad[8];
            ad[0] = pack2(a0.x, a0.x); ad[1] = pack2(a0.y, a0.y);
            ad[2] = pack2(a0.z, a0.z); ad[3] = pack2(a0.w, a0.w);
            ad[4] = pack2(a1.x, a1.x); ad[5] = pack2(a1.y, a1.y);
            ad[6] = pack2(a1.z, a1.z); ad[7] = pack2(a1.w, a1.w);
#pragma unroll
            for (int i = 0; i < 8; i++) {
#pragma unroll
                for (int j = 0; j < 4; j++) ffma2(c[i][j], ad[i], bp[j]);
            }
        }
        __syncthreads();
    }

    float* Cp = Cpart + (size_t)split * 64 * N;
#pragma unroll
    for (int i = 0; i < 8; i++) {
        int m = (i < 4) ? (mA + i) : (mB + i - 4);
#pragma unroll
        for (int j = 0; j < 4; j++) {
            int n = (j < 2) ? (nA + j * 2) : (nB + (j - 2) * 2);
            float lo, hi;
            unpack2(c[i][j], lo, hi);
            *(float2*)(Cp + m * N + n0 + n) = make_float2(lo, hi);
        }
    }
}

// ---------------------------------------------------------------------------
// Classic 64x64 GEMM (kept for N=512 / N=64 cases)
// ---------------------------------------------------------------------------
#define BK 16
#define SST 68

__global__ void __launch_bounds__(256, 2)
gemm64(const float* __restrict__ A, const float* __restrict__ B,
       float* __restrict__ Cpart, int K, int N, int ldb,
       int totalSteps, int stepsPerSplit, int transB) {
    __shared__ __align__(16) float As[BK * SST];
    __shared__ __align__(16) float Bs[BK * SST];
    int tid = threadIdx.x;
    int n0 = blockIdx.x * 64;
    int split = blockIdx.y;
    int s0 = split * stepsPerSplit;
    int s1 = min(s0 + stepsPerSplit, totalSteps);

    float c[4][4] = {};
    int ty = tid >> 4, tx = tid & 15;
    int m0 = ty * 4, nn0 = tx * 4;

    int aRow = tid >> 2;
    int aCol = (tid & 3) * 4;
    int bRow = tid >> 4;
    int bCol = (tid & 15) * 4;

    float4 aR = make_float4(0, 0, 0, 0), bR = make_float4(0, 0, 0, 0);
    if (s0 < s1) {
        int k0 = s0 * BK;
        aR = *(const float4*)(A + aRow * K + k0 + aCol);
        if (!transB) bR = *(const float4*)(B + (k0 + bRow) * ldb + n0 + bCol);
        else         bR = *(const float4*)(B + (n0 + aRow) * ldb + k0 + aCol);
    }
    for (int step = s0; step < s1; ++step) {
        As[(aCol + 0) * SST + aRow] = aR.x;
        As[(aCol + 1) * SST + aRow] = aR.y;
        As[(aCol + 2) * SST + aRow] = aR.z;
        As[(aCol + 3) * SST + aRow] = aR.w;
        if (!transB) {
            *(float4*)(Bs + bRow * SST + bCol) = bR;
        } else {
            Bs[(aCol + 0) * SST + aRow] = bR.x;
            Bs[(aCol + 1) * SST + aRow] = bR.y;
            Bs[(aCol + 2) * SST + aRow] = bR.z;
            Bs[(aCol + 3) * SST + aRow] = bR.w;
        }
        __syncthreads();
        if (step + 1 < s1) {
            int k0 = (step + 1) * BK;
            aR = *(const float4*)(A + aRow * K + k0 + aCol);
            if (!transB) bR = *(const float4*)(B + (k0 + bRow) * ldb + n0 + bCol);
            else         bR = *(const float4*)(B + (n0 + aRow) * ldb + k0 + aCol);
        }
#pragma unroll
        for (int kk = 0; kk < BK; ++kk) {
            float4 a = *(const float4*)(As + kk * SST + m0);
            float4 b = *(const float4*)(Bs + kk * SST + nn0);
            c[0][0] += a.x * b.x; c[0][1] += a.x * b.y; c[0][2] += a.x * b.z; c[0][3] += a.x * b.w;
            c[1][0] += a.y * b.x; c[1][1] += a.y * b.y; c[1][2] += a.y * b.z; c[1][3] += a.y * b.w;
            c[2][0] += a.z * b.x; c[2][1] += a.z * b.y; c[2][2] += a.z * b.z; c[2][3] += a.z * b.w;
            c[3][0] += a.w * b.x; c[3][1] += a.w * b.y; c[3][2] += a.w * b.z; c[3][3] += a.w * b.w;
        }
        __syncthreads();
    }
    float* Cp = Cpart + (size_t)split * 64 * N;
#pragma unroll
    for (int i = 0; i < 4; i++) {
        float4 v = make_float4(c[i][0], c[i][1], c[i][2], c[i][3]);
        *(float4*)(Cp + (m0 + i) * N + n0 + nn0) = v;
    }
}

// ---------------------------------------------------------------------------
// Vectorized combine: sums `splits` partials + optional bias (float4 path).
// ---------------------------------------------------------------------------
__global__ void combine4_kernel(const float* __restrict__ part, const float* __restrict__ bias,
                                float* __restrict__ C, int N, int splits) {
    int idx4 = blockIdx.x * 256 + threadIdx.x;
    int tot4 = 64 * N / 4;
    if (idx4 >= tot4) return;
    float4 s = make_float4(0, 0, 0, 0);
    for (int p = 0; p < splits; p++) {
        float4 v = *(const float4*)(part + (size_t)p * 64 * N + idx4 * 4);
        s.x += v.x; s.y += v.y; s.z += v.z; s.w += v.w;
    }
    if (bias) {
        int n = (idx4 * 4) % N;
        float4 b = *(const float4*)(bias + n);
        s.x += b.x; s.y += b.y; s.z += b.z; s.w += b.w;
    }
    *(float4*)(C + idx4 * 4) = s;
}

// Fused: z1 = sum(part)+b1 ; h = gelu(z1)
__global__ void combine_gelu_kernel(const float* __restrict__ part, const float* __restrict__ bias,
                                    float* __restrict__ z1, float* __restrict__ h, int splits) {
    int idx = blockIdx.x * 256 + threadIdx.x;
    if (idx >= TT * HH) return;
    float s = 0.f;
    for (int p = 0; p < splits; p++) s += part[(size_t)p * TT * HH + idx];
    s += bias[idx % HH];
    z1[idx] = s;
    h[idx] = geluf(s);
}

// Fused: gh = sum(part) ; gz1 = gh * gelu'(z1)
__global__ void combine_gz1_kernel(const float* __restrict__ part, const float* __restrict__ z1,
                                   float* __restrict__ gz1, int splits) {
    int idx = blockIdx.x * 256 + threadIdx.x;
    if (idx >= TT * HH) return;
    float s = 0.f;
    for (int p = 0; p < splits; p++) s += part[(size_t)p * TT * HH + idx];
    gz1[idx] = s * gelugradf(z1[idx]);
}

// ---------------------------------------------------------------------------
// Fused: y = sum(y-partials)+b2 (written out); inv,s per token; gy written.
// One block per token.
// ---------------------------------------------------------------------------
__global__ void invs_gy_kernel(const float* __restrict__ partD, const float* __restrict__ b2,
                               const float* __restrict__ vals, const float* __restrict__ sc,
                               float* __restrict__ y, float* __restrict__ gy,
                               float* __restrict__ invA, float* __restrict__ sA, int splits) {
    int t = blockIdx.x, tid = threadIdx.x;
    __shared__ float buf[DD];
    __shared__ float red[256];
    __shared__ float sh;
    float acc = 0.f;
    for (int d = tid; d < DD; d += 256) {
        float s = b2[d];
        for (int p = 0; p < splits; p++) s += partD[(size_t)p * TT * DD + t * DD + d];
        buf[d] = s; acc += s * s;
    }
    red[tid] = acc; __syncthreads();
    for (int st = 128; st > 0; st >>= 1) { if (tid < st) red[tid] += red[tid + st]; __syncthreads(); }
    if (tid == 0) { sh = rsqrtf(red[0] * (1.0f / DD) + EPSF); invA[t] = sh; }
    __syncthreads();
    float inv = sh;
    acc = 0.f;
    for (int d = tid; d < DD; d += 256) {
        float yv = buf[d], scd = sc[d];
        float gp = 2.f * (yv * inv * scd - vals[t * DD + d]);
        acc += gp * scd * yv;
    }
    __syncthreads();
    red[tid] = acc; __syncthreads();
    for (int st = 128; st > 0; st >>= 1) { if (tid < st) red[tid] += red[tid + st]; __syncthreads(); }
    if (tid == 0) { sA[t] = red[0]; sh = red[0]; }
    __syncthreads();
    float sv = sh;
    float i3 = inv * inv * inv * sv * (1.0f / DD);
    for (int d = tid; d < DD; d += 256) {
        float yv = buf[d], scd = sc[d];
        float gp = 2.f * (yv * inv * scd - vals[t * DD + d]);
        gy[t * DD + d] = inv * scd * gp - i3 * yv;
        y[t * DD + d] = yv;
    }
}

// column sums: gysum[d] = sum_t gy ; scd[d] = sum_t gp*y*inv (scale grad)
__global__ void colsumD_kernel(const float* __restrict__ gy, const float* __restrict__ y,
                               const float* __restrict__ v, const float* __restrict__ sc,
                               const float* __restrict__ invA,
                               float* __restrict__ gysum, float* __restrict__ scd_out) {
    int d = blockIdx.x * 256 + threadIdx.x;
    if (d >= DD) return;
    float gs = 0.f, sd = 0.f;
    float scd = sc[d];
    for (int t = 0; t < TT; t++) {
        int idx = t * DD + d;
        gs += gy[idx];
        float inv = invA[t];
        float yv = y[idx];
        float gp = 2.f * (yv * inv * scd - v[idx]);
        sd += gp * yv * inv;
    }
    gysum[d] = gs; scd_out[d] = sd;
}

__global__ void colsumH_kernel(const float* __restrict__ gz1, float* __restrict__ gz1sum) {
    int h = blockIdx.x * 256 + threadIdx.x;
    if (h >= HH) return;
    float s = 0.f;
    for (int t = 0; t < TT; t++) s += gz1[t * HH + h];
    gz1sum[h] = s;
}

// Fused: C1 row + z1' + gelu -> hp.   hp[t,n] = gelu(z1 - cc*(KK@gz1 + gz1sum))
__global__ void kkgz1_z1p_kernel(const float* __restrict__ KK, const float* __restrict__ gz1,
                                 const float* __restrict__ z1, const float* __restrict__ gz1sum,
                                 float cc, float* __restrict__ hp) {
    int t = blockIdx.x, tid = threadIdx.x;
    __shared__ float row[64];
    if (tid < 64) row[tid] = KK[t * 64 + tid];
    __syncthreads();
    for (int n = tid; n < HH; n += 256) {
        float acc = 0.f;
#pragma unroll 16
        for (int s = 0; s < 64; s++) acc += row[s] * gz1[s * HH + n];
        float z = z1[t * HH + n] - cc * (acc + gz1sum[n]);
        hp[t * HH + n] = geluf(z);
    }
}

// HHm[t,s] = dot(hp[t,:], h[s,:])
__global__ void hh_kernel(const float* __restrict__ hp, const float* __restrict__ h,
                          float* __restrict__ HHm) {
    int t = blockIdx.x, tid = threadIdx.x;
    __shared__ float row[HH];
    for (int j = tid; j < HH; j += 64) row[j] = hp[t * HH + j];
    __syncthreads();
    int s = tid;
    float a0 = 0.f, a1 = 0.f, a2 = 0.f, a3 = 0.f;
    for (int j = 0; j < HH; j += 4) {
        a0 += row[j + 0] * h[s * HH + j + 0];
        a1 += row[j + 1] * h[s * HH + j + 1];
        a2 += row[j + 2] * h[s * HH + j + 2];
        a3 += row[j + 3] * h[s * HH + j + 3];
    }
    HHm[t * 64 + s] = a0 + a1 + a2 + a3;
}

// Final (fused): y'W2 = sum(partials)+b2 ; C2 row = HHm[t,:]@gy ;
// y' = y'W2 - cc*(C2+gysum); pred = rmsnorm(y', sc - cc*scdelta); out = rmsnorm(pred, outsc).
__global__ void final_kernel(const float* __restrict__ partD, const float* __restrict__ b2,
                             const float* __restrict__ HHm, const float* __restrict__ gy,
                             const float* __restrict__ gysum, const float* __restrict__ scdelta,
                             const float* __restrict__ sc, const float* __restrict__ outsc,
                             float cc, float* __restrict__ out, int splits) {
    int t = blockIdx.x, tid = threadIdx.x;
    __shared__ float row[64];
    __shared__ float buf[DD];
    __shared__ float red[256];
    __shared__ float sval;
    if (tid < 64) row[tid] = HHm[t * 64 + tid];
    __syncthreads();
    float acc = 0.f;
    for (int d = tid; d < DD; d += 256) {
        float s = b2[d];
        for (int p = 0; p < splits; p++) s += partD[(size_t)p * TT * DD + t * DD + d];
        float c2 = 0.f;
#pragma unroll 16
        for (int k = 0; k < 64; k++) c2 += row[k] * gy[k * DD + d];
        float v = s - cc * (c2 + gysum[d]);
        buf[d] = v; acc += v * v;
    }
    red[tid] = acc; __syncthreads();
    for (int st = 128; st > 0; st >>= 1) { if (tid < st) red[tid] += red[tid + st]; __syncthreads(); }
    if (tid == 0) sval = rsqrtf(red[0] * (1.0f / DD) + EPSF);
    __syncthreads();
    float inva = sval;
    acc = 0.f;
    for (int d = tid; d < DD; d += 256) {
        float p = buf[d] * inva * (sc[d] - cc * scdelta[d]);
        buf[d] = p; acc += p * p;
    }
    __syncthreads();
    red[tid] = acc; __syncthreads();
    for (int st = 128; st > 0; st >>= 1) { if (tid < st) red[tid] += red[tid + st]; __syncthreads(); }
    if (tid == 0) sval = rsqrtf(red[0] * (1.0f / DD) + EPSF);
    __syncthreads();
    float invb = sval;
    for (int d = tid; d < DD; d += 256)
        out[t * DD + d] = buf[d] * invb * outsc[d];
}

// ---------------------------------------------------------------------------
// Host orchestration
// ---------------------------------------------------------------------------
extern "C" void kernel_launch(void* const* d_in, const int* in_sizes, int n_in,
                              void* d_out, int out_size) {
    const float* x          = (const float*)d_in[0];
    const float* conv_k_w   = (const float*)d_in[1];
    const float* conv_k_b   = (const float*)d_in[2];
    const float* conv_v_w   = (const float*)d_in[3];
    const float* conv_v_b   = (const float*)d_in[4];
    const float* rms_k_sc   = (const float*)d_in[5];
    const float* rms_v_sc   = (const float*)d_in[6];
    const float* dense_k_w  = (const float*)d_in[7];
    const float* dense_k_b  = (const float*)d_in[8];
    const float* dense_v_w  = (const float*)d_in[9];
    const float* dense_v_b  = (const float*)d_in[10];
    const float* mem_w1     = (const float*)d_in[11];
    const float* mem_b1     = (const float*)d_in[12];
    const float* mem_w2     = (const float*)d_in[13];
    const float* mem_b2     = (const float*)d_in[14];
    const float* mem_scale  = (const float*)d_in[15];
    const float* rms_out_sc = (const float*)d_in[16];
    float* out = (float*)d_out;

    float* S = nullptr;
    cudaGetSymbolAddress((void**)&S, g_scratch);

    float* nk     = S + OFF_NK;     float* nv     = S + OFF_NV;
    float* keys   = S + OFF_KEYS;   float* vals   = S + OFF_VALS;
    float* y      = S + OFF_Y;      float* gy     = S + OFF_GY;
    float* part0  = S + OFF_PART0;  float* part1  = S + OFF_PART1;
    float* partD  = S + OFF_PARTD;  float* partH  = S + OFF_PARTH;
    float* z1     = S + OFF_Z1;     float* h      = S + OFF_H;
    float* gz1    = S + OFF_GZ1;    float* hp     = S + OFF_HP;
    float* kkpart = S + OFF_KKPART; float* KK     = S + OFF_KK;
    float* HHm    = S + OFF_HHM;    float* gysum  = S + OFF_GYSUM;
    float* scd    = S + OFF_SCD;    float* gz1sum = S + OFF_GZ1SUM;
    float* invA   = S + OFF_INV;    float* sA     = S + OFF_S;

    float cc = (float)(1e-4 * 0.1 * pow(0.9, 63.0));

    // 1. conv + channel RMSNorm
    conv_rms_kernel<<<TT, 784>>>(x, conv_k_w, conv_k_b, conv_v_w, conv_v_b,
                                 rms_k_sc, rms_v_sc, nk, nv);

    // 2. keys / vals big GEMMs (wide FFMA2 kernel, split-K=14, 196 CTAs)
    gemmw<<<dim3(14, 14), 224>>>(nk, dense_k_w, part0, DD, DD, DD, 196, 14);
    gemmw<<<dim3(14, 14), 224>>>(nv, dense_v_w, part1, DD, DD, DD, 196, 14);
    combine4_kernel<<<196, 256>>>(part0, dense_k_b, keys, DD, 14);
    combine4_kernel<<<196, 256>>>(part1, dense_v_b, vals, DD, 14);

    // 3. z1 = keys @ W1 + b1 ; h = gelu(z1)
    gemm64<<<dim3(8, 18), 256>>>(keys, mem_w1, partH, DD, HH, HH, 196, 11, 0);
    combine_gelu_kernel<<<128, 256>>>(partH, mem_b1, z1, h, 18);

    // 4. y = h @ W2 + b2 (wide kernel, split-K=8) ; fused combine+inv,s+gy
    gemmw<<<dim3(14, 8), 224>>>(h, mem_w2, partD, HH, DD, DD, 32, 4);
    invs_gy_kernel<<<TT, 256>>>(partD, mem_b2, vals, mem_scale, y, gy, invA, sA, 8);
    colsumD_kernel<<<13, 256>>>(gy, y, vals, mem_scale, invA, gysum, scd);

    // 5. gh = gy @ W2^T ; gz1 = gh * gelu'(z1)
    gemm64<<<dim3(8, 18), 256>>>(gy, mem_w2, partH, DD, HH, DD, 196, 11, 1);
    combine_gz1_kernel<<<128, 256>>>(partH, z1, gz1, 18);
    colsumH_kernel<<<2, 256>>>(gz1, gz1sum);

    // 6. KK = keys @ keys^T ; hp = gelu(z1 - cc*(KK@gz1 + gz1sum))
    gemm64<<<dim3(1, 49), 256>>>(keys, keys, kkpart, DD, 64, DD, 196, 4, 1);
    combine4_kernel<<<4, 256>>>(kkpart, nullptr, KK, 64, 49);
    kkgz1_z1p_kernel<<<TT, 256>>>(KK, gz1, z1, gz1sum, cc, hp);

    // 7. y'W2 partials ; HHm = hp @ h^T ; fused final (combine + C2 + 2x rmsnorm)
    gemmw<<<dim3(14, 8), 224>>>(hp, mem_w2, partD, HH, DD, DD, 32, 4);
    hh_kernel<<<TT, 64>>>(hp, h, HHm);
    final_kernel<<<TT, 256>>>(partD, mem_b2, HHm, gy, gysum, scd, mem_scale,
                              rms_out_sc, cc, out, 8);

    (void)in_sizes; (void)n_in; (void)out_size;
}